// round 10
// baseline (speedup 1.0000x reference)
#include <cuda_runtime.h>
#include <cuda_fp16.h>
#include <cstdint>

// ============================================================================
// 3-layer MLP via mma.sync.m16n8k16.f32.f16.f16.f32 on sm_103a.
//   out = relu(relu(x@w1+b1)@w2+b2)@w3+b3
// fp16 operands (11-bit mantissa = tf32 class), f32 accumulate, full-rate
// HMMA pipe (~613 TF/s measured implied peak).
// CTA 128x256, 256 threads, 8 warps in 2(M)x4(N) grid, warp tile 64x64
// (minimizes smem fragment duplication: 32KB reads + 12KB writes per kt
// vs 256-cyc tensor floor -> crossbar cap 73%, up from 53% at 64x32).
// BK=16, 8-stage cp.async ring (96KB), persistent CTAs with seamless
// cross-tile pipelining (ktiles%8==0: tail kts prefetch the next tile).
// Operand layout: within each 16-element K-group, logical k stored at
//   hperm(k) = 4*((k>>1)&3) + 2*(k>>3) + (k&1)
// so each mma fragment (a0,a2 / a1,a3 / b0,b1) is ONE conflict-free lds.64.
// h1/h2 live as permuted fp16 in gmem. All conversions round-to-nearest.
// ============================================================================

#define DINL __device__ __forceinline__

constexpr int BATCH = 4096, IN = 2048, HID = 4096, NCLS = 1000, NCLS_PAD = 1024;

constexpr int BM = 128, BN = 256, BK = 16;
constexpr int STAGES = 8;
constexpr int A_ST = BM * BK * 2;           // 4096 B
constexpr int B_ST = BN * BK * 2;           // 8192 B
constexpr int B_OFF = STAGES * A_ST;        // 32768
constexpr int SMEM_TOT = STAGES * (A_ST + B_ST);   // 98304 B

constexpr int MF = 4, NF = 8;               // warp tile 64 x 64
constexpr int NSM = 152;
constexpr int GRID = NSM;                   // 1 CTA/SM persistent

// device scratch (allocation-guard-safe), fp16 permuted layouts
__device__ __half g_h1 [(size_t)BATCH * HID];
__device__ __half g_h2 [(size_t)BATCH * HID];
__device__ __half g_xr [(size_t)BATCH * IN];
__device__ __half g_w1t[(size_t)HID * IN];
__device__ __half g_w2t[(size_t)HID * HID];
__device__ __half g_w3t[(size_t)NCLS_PAD * HID];

// ---------------------------------------------------------------- helpers
DINL uint32_t s2u(const void* p) {
    uint32_t a;
    asm("{ .reg .u64 t; cvta.to.shared.u64 t, %1; cvt.u32.u64 %0, t; }"
        : "=r"(a) : "l"(p));
    return a;
}
DINL void cp_async16(uint32_t s, const void* g) {
    asm volatile("cp.async.cg.shared.global [%0], [%1], 16;" :: "r"(s), "l"(g));
}
DINL void cp_commit() { asm volatile("cp.async.commit_group;" ::: "memory"); }
#define CP_WAIT(n) asm volatile("cp.async.wait_group %0;" :: "n"(n) : "memory")

DINL uint2 lds64(uint32_t a) {
    uint2 v;
    asm volatile("ld.shared.v2.b32 {%0,%1}, [%2];"
                 : "=r"(v.x), "=r"(v.y) : "r"(a));
    return v;
}
DINL void mma16816(float* d, uint32_t a0, uint32_t a1, uint32_t a2, uint32_t a3,
                   uint32_t b0, uint32_t b1) {
    asm volatile(
        "mma.sync.aligned.m16n8k16.row.col.f32.f16.f16.f32 "
        "{%0,%1,%2,%3}, {%4,%5,%6,%7}, {%8,%9}, {%0,%1,%2,%3};"
        : "+f"(d[0]), "+f"(d[1]), "+f"(d[2]), "+f"(d[3])
        : "r"(a0), "r"(a1), "r"(a2), "r"(a3), "r"(b0), "r"(b1));
}
// fp16 K-permutation: logical j (0..15) -> phys 4*((j>>1)&3) + 2*(j>>3) + (j&1)
DINL int hperm16(int j) { return 4 * ((j >> 1) & 3) + 2 * ((j >> 3) & 1) + (j & 1); }

// ------------------------------------------------------------------ GEMM
// A [M,K] fp16 row-major (hperm16 within 16-groups), Bt [Npad,K] fp16 same,
// Cv: fp16 (permuted, layers 1/2) or f32 plain (layer 3).
// flags: bit0 relu, bit1 fp16-permuted output (else f32 plain).
__global__ __launch_bounds__(256, 1)
void mlp_gemm_h(const __half* __restrict__ A, const __half* __restrict__ Bt,
                const float* __restrict__ bias, void* __restrict__ Cv,
                int K, int N, int Mt, int Nt, int flags) {
    extern __shared__ char smem[];
    const uint32_t sb = s2u(smem);
    const int tid = threadIdx.x;
    const int wid = tid >> 5, lid = tid & 31;
    const int warp_m = wid & 1;           // 0..1  (64 rows)
    const int warp_n = wid >> 1;          // 0..3  (64 cols)
    const int lg = lid >> 2;              // 0..7
    const int lc = lid & 3;               // 0..3
    const int ktiles = K / BK;
    const int ntile = Mt * Nt;
    const int do_relu = flags & 1, do_h16 = flags & 2;

    int idx = blockIdx.x;
    if (idx >= ntile) return;

    // cp.async: A 256 chunks (1/thread), B 512 chunks (2/thread)
    auto load_stage = [&](const __half* Ag, const __half* Bg, int kt, int buf) {
        const __half* ap = Ag + kt * BK;
        const uint32_t ab = sb + buf * A_ST;
        {
            const int row = tid >> 1, j = tid & 1;      // 128 rows x 2
            cp_async16(ab + row * 32 + j * 16, ap + (size_t)row * K + j * 8);
        }
        const __half* bp = Bg + kt * BK;
        const uint32_t bb = sb + B_OFF + buf * B_ST;
#pragma unroll
        for (int t = 0; t < 2; t++) {
            const int ch = tid + t * 256;
            const int row = ch >> 1, j = ch & 1;        // 256 rows x 2
            cp_async16(bb + row * 32 + j * 16, bp + (size_t)row * K + j * 8);
        }
    };

    int m0 = (idx % Mt) * BM, n0 = (idx / Mt) * BN;
    const __half* Ag = A + (size_t)m0 * K;
    const __half* Bg = Bt + (size_t)n0 * K;

    for (int s = 0; s < STAGES - 1; s++) { load_stage(Ag, Bg, s, s); cp_commit(); }

    // fragment base byte addrs (buffer 0); rows are 32B
    const uint32_t a_t0 = sb + (warp_m * 64 + lg) * 32 + 8 * lc;
    const uint32_t b_t0 = sb + B_OFF + (warp_n * 64 + lg) * 32 + 8 * lc;

    for (;;) {
        const int nidx = idx + GRID;
        const int valid = nidx < ntile;
        const __half* Agn = valid ? A + (size_t)((nidx % Mt) * BM) * K : Ag;
        const __half* Bgn = valid ? Bt + (size_t)((nidx / Mt) * BN) * K : Bg;

        float acc[MF][NF][4];
#pragma unroll
        for (int i = 0; i < MF; i++)
#pragma unroll
            for (int j = 0; j < NF; j++)
#pragma unroll
                for (int r = 0; r < 4; r++) acc[i][j][r] = 0.f;

        for (int kt = 0; kt < ktiles; kt++) {
            const int b = kt & (STAGES - 1);
            CP_WAIT(STAGES - 2);
            __syncthreads();

            const int nk = kt + STAGES - 1;
            if (nk < ktiles)  load_stage(Ag, Bg, nk, nk & (STAGES - 1));
            else if (valid)   load_stage(Agn, Bgn, nk - ktiles, nk & (STAGES - 1));
            cp_commit();

            const uint32_t ab = a_t0 + b * A_ST;
            const uint32_t bb = b_t0 + b * B_ST;

            uint2 af[MF][2];
#pragma unroll
            for (int mf = 0; mf < MF; mf++) {
                af[mf][0] = lds64(ab + mf * 512);        // row lg   -> a0,a2
                af[mf][1] = lds64(ab + mf * 512 + 256);  // row lg+8 -> a1,a3
            }
            uint2 bf[NF];
#pragma unroll
            for (int nf = 0; nf < NF; nf++)
                bf[nf] = lds64(bb + nf * 256);           // col lg   -> b0,b1
#pragma unroll
            for (int mf = 0; mf < MF; mf++)
#pragma unroll
                for (int nf = 0; nf < NF; nf++)
                    mma16816(acc[mf][nf], af[mf][0].x, af[mf][1].x,
                             af[mf][0].y, af[mf][1].y, bf[nf].x, bf[nf].y);
        }

        // ---- epilogue (next tile's stages already streaming)
        float bvv[NF][2];
#pragma unroll
        for (int nf = 0; nf < NF; nf++) {
            const int c = n0 + warp_n * 64 + nf * 8 + 2 * lc;
            bvv[nf][0] = (c < N) ? __ldg(bias + c) : 0.f;
            bvv[nf][1] = (c + 1 < N) ? __ldg(bias + c + 1) : 0.f;
        }
#pragma unroll
        for (int mf = 0; mf < MF; mf++) {
#pragma unroll
            for (int r2 = 0; r2 < 2; r2++) {
                const int m = m0 + warp_m * 64 + mf * 16 + lg + r2 * 8;
#pragma unroll
                for (int nf = 0; nf < NF; nf++) {
                    const int c = n0 + warp_n * 64 + nf * 8 + 2 * lc;
                    float v0 = acc[mf][nf][r2 * 2 + 0] + bvv[nf][0];
                    float v1 = acc[mf][nf][r2 * 2 + 1] + bvv[nf][1];
                    if (do_relu) { v0 = fmaxf(v0, 0.f); v1 = fmaxf(v1, 0.f); }
                    if (do_h16) {
                        // store into hperm16-permuted fp16 layout:
                        // logical pair (c,c+1), c = 8*(nf&1)+2*lc (mod 16)
                        // -> phys pair base 4*lc + 2*(nf&1)
                        __half* crow = (__half*)Cv + (size_t)m * N;
                        const int pidx = (c & ~15) + 4 * lc + 2 * (nf & 1);
                        *(__half2*)(crow + pidx) = __floats2half2_rn(v0, v1);
                    } else if (c < N) {
                        float* crow = (float*)Cv + (size_t)m * N;
                        *(float2*)(crow + c) = make_float2(v0, v1);
                    }
                }
            }
        }

        if (!valid) break;
        idx = nidx;
        m0 = (idx % Mt) * BM; n0 = (idx / Mt) * BN;
        Ag = Agn; Bg = Bgn;
    }
}

// ---------------------------------------------------- fused prep (1 launch)
__device__ void transpose_job(const float* __restrict__ s, __half* __restrict__ d,
                              int R, int C, int bx, int by) {
    __shared__ float t[32][33];
    const int tid = threadIdx.x;
    const int x = tid & 31, y = tid >> 5;   // 32 x 8
    const int c0 = bx * 32, r0 = by * 32;
#pragma unroll
    for (int i = y; i < 32; i += 8) {
        int r = r0 + i, c = c0 + x;
        t[i][x] = (c < C) ? s[(size_t)r * C + c] : 0.f;
    }
    __syncthreads();
#pragma unroll
    for (int i = y; i < 32; i += 8) {
        int cc = c0 + i, rr = r0 + x;        // cc = out row (N), rr = K pos
        int rp = (rr & ~15) | hperm16(rr & 15);
        d[(size_t)cc * R + rp] = __float2half_rn(t[x][i]);
    }
}

constexpr int G_W1 = (HID / 32) * (IN / 32);        // 8192
constexpr int G_W2 = (HID / 32) * (HID / 32);       // 16384
constexpr int G_W3 = (NCLS_PAD / 32) * (HID / 32);  // 4096
constexpr int G_X  = (BATCH * IN) / 4096;           // 2048
constexpr int G_PREP = G_W1 + G_W2 + G_W3 + G_X;

__global__ __launch_bounds__(256)
void prep_all(const float* __restrict__ w1, const float* __restrict__ w2,
              const float* __restrict__ w3, const float* __restrict__ x,
              __half* __restrict__ w1t, __half* __restrict__ w2t,
              __half* __restrict__ w3t, __half* __restrict__ xr) {
    int id = blockIdx.x;
    if (id < G_W1) {
        transpose_job(w1, w1t, IN, HID, id % (HID / 32), id / (HID / 32));
        return;
    }
    id -= G_W1;
    if (id < G_W2) {
        transpose_job(w2, w2t, HID, HID, id % (HID / 32), id / (HID / 32));
        return;
    }
    id -= G_W2;
    if (id < G_W3) {
        transpose_job(w3, w3t, HID, NCLS, id % (NCLS_PAD / 32), id / (NCLS_PAD / 32));
        return;
    }
    id -= G_W3;
    // x: fp16-convert + hperm16; 16 floats/thread (one K-group)
    const size_t base = (size_t)id * 4096 + threadIdx.x * 16;
    float f[16];
#pragma unroll
    for (int i = 0; i < 16; i += 4) *(float4*)&f[i] = *(const float4*)(x + base + i);
    __half2 o[8];
#pragma unroll
    for (int j = 0; j < 8; j++) {
        const int l = 8 * (j & 1) + 2 * (j >> 1);   // phys pair (2j,2j+1) <- logical (l,l+1)
        o[j] = __floats2half2_rn(f[l], f[l + 1]);
    }
    *(uint4*)(xr + base)     = *(uint4*)&o[0];
    *(uint4*)(xr + base + 8) = *(uint4*)&o[4];
}

// ----------------------------------------------------------------- launcher
extern "C" void kernel_launch(void* const* d_in, const int* in_sizes, int n_in,
                              void* d_out, int out_size) {
    (void)in_sizes; (void)n_in; (void)out_size;
    const float* x  = (const float*)d_in[0];
    const float* w1 = (const float*)d_in[1];
    const float* b1 = (const float*)d_in[2];
    const float* w2 = (const float*)d_in[3];
    const float* b2 = (const float*)d_in[4];
    const float* w3 = (const float*)d_in[5];
    const float* b3 = (const float*)d_in[6];

    __half *h1, *h2, *xr, *w1t, *w2t, *w3t;
    cudaGetSymbolAddress((void**)&h1,  g_h1);
    cudaGetSymbolAddress((void**)&h2,  g_h2);
    cudaGetSymbolAddress((void**)&xr,  g_xr);
    cudaGetSymbolAddress((void**)&w1t, g_w1t);
    cudaGetSymbolAddress((void**)&w2t, g_w2t);
    cudaGetSymbolAddress((void**)&w3t, g_w3t);

    cudaFuncSetAttribute(mlp_gemm_h,
                         cudaFuncAttributeMaxDynamicSharedMemorySize, SMEM_TOT);

    prep_all<<<G_PREP, 256>>>(w1, w2, w3, x, w1t, w2t, w3t, xr);

    const int MT = BATCH / BM;                 // 32
    mlp_gemm_h<<<GRID, 256, SMEM_TOT>>>(
        xr, w1t, b1, h1, IN, HID, MT, HID / BN, /*relu|h16*/ 3);
    mlp_gemm_h<<<GRID, 256, SMEM_TOT>>>(
        h1, w2t, b2, h2, HID, HID, MT, HID / BN, 3);
    mlp_gemm_h<<<GRID, 256, SMEM_TOT>>>(
        h2, w3t, b3, d_out, HID, NCLS, MT, NCLS_PAD / BN, 0);
}

// round 13
// speedup vs baseline: 1.1451x; 1.1451x over previous
#include <cuda_runtime.h>
#include <cuda_fp16.h>
#include <cstdint>

// ============================================================================
// 3-layer MLP via mma.sync.m16n8k16.f32.f16.f16.f32 on sm_103a.
//   out = relu(relu(x@w1+b1)@w2+b2)@w3+b3
// CTA 128x256, 256 threads, 8 warps (2Mx4N), warp tile 64x64.
// BK=32 (two k16 mma groups per step): halves barrier/pipeline overhead per
// FLOP vs BK=16 -- the diagnosed 26% loss at BK=16 was per-kt convoy cost.
// 4-stage cp.async ring (96KB), persistent CTAs, seamless cross-tile
// prefetch (ktiles%4==0 everywhere).
// K-layout: within each 32-element K-group, logical k stored at
//   perm32(k) = 8*(((k&15)>>1)&3) + 4*(k>>4) + 2*((k>>3)&1) + (k&1)
// so thread lc's A/B fragments for BOTH k16 groups are one 16B chunk at
// offset row*64 + 16*lc  ->  ONE conflict-free lds.128 per fragment row
// (each 8-lane phase covers one 128B stretch exactly).
// fp16 operands (11-bit mantissa = tf32 class), f32 accumulate; h1/h2 are
// permuted fp16 in gmem; all conversions round-to-nearest.
// ============================================================================

#define DINL __device__ __forceinline__

constexpr int BATCH = 4096, IN = 2048, HID = 4096, NCLS = 1000, NCLS_PAD = 1024;

constexpr int BM = 128, BN = 256, BK = 32;
constexpr int STAGES = 4;
constexpr int A_ST = BM * BK * 2;           // 8192 B
constexpr int B_ST = BN * BK * 2;           // 16384 B
constexpr int B_OFF = STAGES * A_ST;        // 32768
constexpr int SMEM_TOT = STAGES * (A_ST + B_ST);   // 98304 B

constexpr int MF = 4, NF = 8;               // warp tile 64 x 64
constexpr int NSM = 152;
constexpr int GRID = NSM;                   // 1 CTA/SM persistent

// device scratch (allocation-guard-safe), fp16 perm32 layouts
__device__ __half g_h1 [(size_t)BATCH * HID];
__device__ __half g_h2 [(size_t)BATCH * HID];
__device__ __half g_xr [(size_t)BATCH * IN];
__device__ __half g_w1t[(size_t)HID * IN];
__device__ __half g_w2t[(size_t)HID * HID];
__device__ __half g_w3t[(size_t)NCLS_PAD * HID];

// ---------------------------------------------------------------- helpers
DINL uint32_t s2u(const void* p) {
    uint32_t a;
    asm("{ .reg .u64 t; cvta.to.shared.u64 t, %1; cvt.u32.u64 %0, t; }"
        : "=r"(a) : "l"(p));
    return a;
}
DINL void cp_async16(uint32_t s, const void* g) {
    asm volatile("cp.async.cg.shared.global [%0], [%1], 16;" :: "r"(s), "l"(g));
}
DINL void cp_commit() { asm volatile("cp.async.commit_group;" ::: "memory"); }
#define CP_WAIT(n) asm volatile("cp.async.wait_group %0;" :: "n"(n) : "memory")

DINL uint4 lds128(uint32_t a) {
    uint4 v;
    asm volatile("ld.shared.v4.b32 {%0,%1,%2,%3}, [%4];"
                 : "=r"(v.x), "=r"(v.y), "=r"(v.z), "=r"(v.w) : "r"(a));
    return v;
}
DINL void mma16816(float* d, uint32_t a0, uint32_t a1, uint32_t a2, uint32_t a3,
                   uint32_t b0, uint32_t b1) {
    asm volatile(
        "mma.sync.aligned.m16n8k16.row.col.f32.f16.f16.f32 "
        "{%0,%1,%2,%3}, {%4,%5,%6,%7}, {%8,%9}, {%0,%1,%2,%3};"
        : "+f"(d[0]), "+f"(d[1]), "+f"(d[2]), "+f"(d[3])
        : "r"(a0), "r"(a1), "r"(a2), "r"(a3), "r"(b0), "r"(b1));
}
// 32-wide K-permutation (see header comment)
DINL int perm32(int j) {
    const int jj = j & 15;
    return 8 * ((jj >> 1) & 3) + 4 * ((j >> 4) & 1) + 2 * ((jj >> 3) & 1) + (jj & 1);
}

// ------------------------------------------------------------------ GEMM
// A [M,K] fp16 row-major (perm32 within 32-groups), Bt [Npad,K] fp16 same,
// Cv: fp16 (perm32, layers 1/2) or f32 plain (layer 3).
// flags: bit0 relu, bit1 fp16-perm32 output (else f32 plain).
__global__ __launch_bounds__(256, 1)
void mlp_gemm_h(const __half* __restrict__ A, const __half* __restrict__ Bt,
                const float* __restrict__ bias, void* __restrict__ Cv,
                int K, int N, int Mt, int Nt, int flags) {
    extern __shared__ char smem[];
    const uint32_t sb = s2u(smem);
    const int tid = threadIdx.x;
    const int wid = tid >> 5, lid = tid & 31;
    const int warp_m = wid & 1;           // 0..1  (64 rows)
    const int warp_n = wid >> 1;          // 0..3  (64 cols)
    const int lg = lid >> 2;              // 0..7
    const int lc = lid & 3;               // 0..3
    const int ktiles = K / BK;
    const int ntile = Mt * Nt;
    const int do_relu = flags & 1, do_h16 = flags & 2;

    int idx = blockIdx.x;
    if (idx >= ntile) return;

    // cp.async: A 512 chunks of 16B (2/thread), B 1024 chunks (4/thread);
    // rows are 64B (32 fp16).
    auto load_stage = [&](const __half* Ag, const __half* Bg, int kt, int buf) {
        const __half* ap = Ag + kt * BK;
        const uint32_t ab = sb + buf * A_ST;
#pragma unroll
        for (int t = 0; t < 2; t++) {
            const int ch = tid + t * 256;
            const int row = ch >> 2, j = ch & 3;
            cp_async16(ab + row * 64 + j * 16, ap + (size_t)row * K + j * 8);
        }
        const __half* bp = Bg + kt * BK;
        const uint32_t bb = sb + B_OFF + buf * B_ST;
#pragma unroll
        for (int t = 0; t < 4; t++) {
            const int ch = tid + t * 256;
            const int row = ch >> 2, j = ch & 3;
            cp_async16(bb + row * 64 + j * 16, bp + (size_t)row * K + j * 8);
        }
    };

    int m0 = (idx % Mt) * BM, n0 = (idx / Mt) * BN;
    const __half* Ag = A + (size_t)m0 * K;
    const __half* Bg = Bt + (size_t)n0 * K;

    for (int s = 0; s < STAGES - 1; s++) { load_stage(Ag, Bg, s, s); cp_commit(); }

    // fragment base byte addrs (buffer 0); rows are 64B
    const uint32_t a_t0 = sb + (warp_m * 64 + lg) * 64 + 16 * lc;
    const uint32_t b_t0 = sb + B_OFF + (warp_n * 64 + lg) * 64 + 16 * lc;

    for (;;) {
        const int nidx = idx + GRID;
        const int valid = nidx < ntile;
        const __half* Agn = valid ? A + (size_t)((nidx % Mt) * BM) * K : Ag;
        const __half* Bgn = valid ? Bt + (size_t)((nidx / Mt) * BN) * K : Bg;

        float acc[MF][NF][4];
#pragma unroll
        for (int i = 0; i < MF; i++)
#pragma unroll
            for (int j = 0; j < NF; j++)
#pragma unroll
                for (int r = 0; r < 4; r++) acc[i][j][r] = 0.f;

        for (int kt = 0; kt < ktiles; kt++) {
            const int b = kt & (STAGES - 1);
            CP_WAIT(STAGES - 2);
            __syncthreads();

            const int nk = kt + STAGES - 1;
            if (nk < ktiles)  load_stage(Ag, Bg, nk, nk & (STAGES - 1));
            else if (valid)   load_stage(Agn, Bgn, nk - ktiles, nk & (STAGES - 1));
            cp_commit();

            const uint32_t ab = a_t0 + b * A_ST;
            const uint32_t bb = b_t0 + b * B_ST;

            // one lds.128 per fragment row covers BOTH k16 groups:
            //   .x = {a0,a1} g0   .y = {a2,a3} g0   .z,.w = same for g1
            uint4 af[MF][2];
#pragma unroll
            for (int mf = 0; mf < MF; mf++) {
                af[mf][0] = lds128(ab + mf * 1024);        // row lg
                af[mf][1] = lds128(ab + mf * 1024 + 512);  // row lg+8
            }
            uint4 bf[NF];
#pragma unroll
            for (int nf = 0; nf < NF; nf++)
                bf[nf] = lds128(bb + nf * 512);            // col lg
#pragma unroll
            for (int mf = 0; mf < MF; mf++)
#pragma unroll
                for (int nf = 0; nf < NF; nf++) {
                    mma16816(acc[mf][nf], af[mf][0].x, af[mf][1].x,
                             af[mf][0].y, af[mf][1].y, bf[nf].x, bf[nf].y);
                    mma16816(acc[mf][nf], af[mf][0].z, af[mf][1].z,
                             af[mf][0].w, af[mf][1].w, bf[nf].z, bf[nf].w);
                }
        }

        // ---- epilogue (next tile's stages already streaming)
        float bvv[NF][2];
#pragma unroll
        for (int nf = 0; nf < NF; nf++) {
            const int c = n0 + warp_n * 64 + nf * 8 + 2 * lc;
            bvv[nf][0] = (c < N) ? __ldg(bias + c) : 0.f;
            bvv[nf][1] = (c + 1 < N) ? __ldg(bias + c + 1) : 0.f;
        }
#pragma unroll
        for (int mf = 0; mf < MF; mf++) {
#pragma unroll
            for (int r2 = 0; r2 < 2; r2++) {
                const int m = m0 + warp_m * 64 + mf * 16 + lg + r2 * 8;
#pragma unroll
                for (int nf = 0; nf < NF; nf++) {
                    const int c = n0 + warp_n * 64 + nf * 8 + 2 * lc;
                    float v0 = acc[mf][nf][r2 * 2 + 0] + bvv[nf][0];
                    float v1 = acc[mf][nf][r2 * 2 + 1] + bvv[nf][1];
                    if (do_relu) { v0 = fmaxf(v0, 0.f); v1 = fmaxf(v1, 0.f); }
                    if (do_h16) {
                        // perm32 slot of logical pair (c,c+1), c even:
                        // phys = 8*lc + 4*((nf>>1)&1) + 2*(nf&1)
                        __half* crow = (__half*)Cv + (size_t)m * N;
                        const int pidx = (c & ~31) + 8 * lc +
                                         4 * ((nf >> 1) & 1) + 2 * (nf & 1);
                        *(__half2*)(crow + pidx) = __floats2half2_rn(v0, v1);
                    } else if (c < N) {
                        float* crow = (float*)Cv + (size_t)m * N;
                        *(float2*)(crow + c) = make_float2(v0, v1);
                    }
                }
            }
        }

        if (!valid) break;
        idx = nidx;
        m0 = (idx % Mt) * BM; n0 = (idx / Mt) * BN;
        Ag = Agn; Bg = Bgn;
    }
}

// ---------------------------------------------------- fused prep (1 launch)
__device__ void transpose_job(const float* __restrict__ s, __half* __restrict__ d,
                              int R, int C, int bx, int by) {
    __shared__ float t[32][33];
    const int tid = threadIdx.x;
    const int x = tid & 31, y = tid >> 5;   // 32 x 8
    const int c0 = bx * 32, r0 = by * 32;
#pragma unroll
    for (int i = y; i < 32; i += 8) {
        int r = r0 + i, c = c0 + x;
        t[i][x] = (c < C) ? s[(size_t)r * C + c] : 0.f;
    }
    __syncthreads();
#pragma unroll
    for (int i = y; i < 32; i += 8) {
        int cc = c0 + i, rr = r0 + x;        // cc = out row (N), rr = K pos
        int rp = (rr & ~31) | perm32(rr & 31);
        d[(size_t)cc * R + rp] = __float2half_rn(t[x][i]);
    }
}

constexpr int G_W1 = (HID / 32) * (IN / 32);        // 8192
constexpr int G_W2 = (HID / 32) * (HID / 32);       // 16384
constexpr int G_W3 = (NCLS_PAD / 32) * (HID / 32);  // 4096
constexpr int G_X  = (BATCH * IN) / 8192;           // 1024 (32 floats/thread)
constexpr int G_PREP = G_W1 + G_W2 + G_W3 + G_X;

__global__ __launch_bounds__(256)
void prep_all(const float* __restrict__ w1, const float* __restrict__ w2,
              const float* __restrict__ w3, const float* __restrict__ x,
              __half* __restrict__ w1t, __half* __restrict__ w2t,
              __half* __restrict__ w3t, __half* __restrict__ xr) {
    int id = blockIdx.x;
    if (id < G_W1) {
        transpose_job(w1, w1t, IN, HID, id % (HID / 32), id / (HID / 32));
        return;
    }
    id -= G_W1;
    if (id < G_W2) {
        transpose_job(w2, w2t, HID, HID, id % (HID / 32), id / (HID / 32));
        return;
    }
    id -= G_W2;
    if (id < G_W3) {
        transpose_job(w3, w3t, HID, NCLS, id % (NCLS_PAD / 32), id / (NCLS_PAD / 32));
        return;
    }
    id -= G_W3;
    // x: fp16-convert + perm32; 32 floats/thread (one K-group)
    const size_t base = (size_t)id * 8192 + threadIdx.x * 32;
    float f[32];
#pragma unroll
    for (int i = 0; i < 32; i += 4) *(float4*)&f[i] = *(const float4*)(x + base + i);
    __half h[32];
#pragma unroll
    for (int j = 0; j < 32; j++) h[perm32(j)] = __float2half_rn(f[j]);
#pragma unroll
    for (int i = 0; i < 4; i++)
        *(uint4*)(xr + base + i * 8) = *(uint4*)&h[i * 8];
}

// ----------------------------------------------------------------- launcher
extern "C" void kernel_launch(void* const* d_in, const int* in_sizes, int n_in,
                              void* d_out, int out_size) {
    (void)in_sizes; (void)n_in; (void)out_size;
    const float* x  = (const float*)d_in[0];
    const float* w1 = (const float*)d_in[1];
    const float* b1 = (const float*)d_in[2];
    const float* w2 = (const float*)d_in[3];
    const float* b2 = (const float*)d_in[4];
    const float* w3 = (const float*)d_in[5];
    const float* b3 = (const float*)d_in[6];

    __half *h1, *h2, *xr, *w1t, *w2t, *w3t;
    cudaGetSymbolAddress((void**)&h1,  g_h1);
    cudaGetSymbolAddress((void**)&h2,  g_h2);
    cudaGetSymbolAddress((void**)&xr,  g_xr);
    cudaGetSymbolAddress((void**)&w1t, g_w1t);
    cudaGetSymbolAddress((void**)&w2t, g_w2t);
    cudaGetSymbolAddress((void**)&w3t, g_w3t);

    cudaFuncSetAttribute(mlp_gemm_h,
                         cudaFuncAttributeMaxDynamicSharedMemorySize, SMEM_TOT);

    prep_all<<<G_PREP, 256>>>(w1, w2, w3, x, w1t, w2t, w3t, xr);

    const int MT = BATCH / BM;                 // 32
    mlp_gemm_h<<<GRID, 256, SMEM_TOT>>>(
        xr, w1t, b1, h1, IN, HID, MT, HID / BN, /*relu|h16*/ 3);
    mlp_gemm_h<<<GRID, 256, SMEM_TOT>>>(
        h1, w2t, b2, h2, HID, HID, MT, HID / BN, 3);
    mlp_gemm_h<<<GRID, 256, SMEM_TOT>>>(
        h2, w3t, b3, d_out, HID, NCLS, MT, NCLS_PAD / BN, 0);
}

// round 14
// speedup vs baseline: 1.2413x; 1.0840x over previous
#include <cuda_runtime.h>
#include <cuda_fp16.h>
#include <cstdint>

// ============================================================================
// 3-layer MLP via mma.sync.m16n8k16.f32.f16.f16.f32 on sm_103a.
//   out = relu(relu(x@w1+b1)@w2+b2)@w3+b3
// CTA 128x256, 256 threads, 8 warps (2Mx4N), warp tile 64x64.
// BK=64: each pipeline stage = two contiguous BK=32 sub-stages, ONE
// CP_WAIT+__syncthreads per 4096 mma-cycles (overhead ~7%, was ~12% at
// BK=32, ~26% at BK=16 -- measured 1/BK law).
// 4-stage cp.async ring (192KB smem), persistent CTAs, seamless cross-tile
// prefetch (ktiles%4==0 everywhere).
// K-layout per 32-group: logical k stored at
//   perm32(k) = 8*(((k&15)>>1)&3) + 4*(k>>4) + 2*((k>>3)&1) + (k&1)
// -> thread lc's A/B fragments for both k16 halves of a 32-group are one
// 16B chunk at row*64 + 16*lc: ONE conflict-free lds.128 per fragment row.
// fp16 operands (11-bit mantissa = tf32 class), f32 accumulate; h1/h2 are
// perm32 fp16 in gmem; all conversions round-to-nearest.
// ============================================================================

#define DINL __device__ __forceinline__

constexpr int BATCH = 4096, IN = 2048, HID = 4096, NCLS = 1000, NCLS_PAD = 1024;

constexpr int BM = 128, BN = 256, BK = 64;
constexpr int STAGES = 4;
constexpr int A_HALF = BM * 32 * 2;         // 8192 B  (one 32-wide sub-stage)
constexpr int B_HALF = BN * 32 * 2;         // 16384 B
constexpr int A_ST = 2 * A_HALF;            // 16384 B
constexpr int B_ST = 2 * B_HALF;            // 32768 B
constexpr int B_OFF = STAGES * A_ST;        // 65536
constexpr int SMEM_TOT = STAGES * (A_ST + B_ST);   // 196608 B (192KB)

constexpr int MF = 4, NF = 8;               // warp tile 64 x 64
constexpr int NSM = 152;
constexpr int GRID = NSM;                   // 1 CTA/SM persistent

// device scratch (allocation-guard-safe), fp16 perm32 layouts
__device__ __half g_h1 [(size_t)BATCH * HID];
__device__ __half g_h2 [(size_t)BATCH * HID];
__device__ __half g_xr [(size_t)BATCH * IN];
__device__ __half g_w1t[(size_t)HID * IN];
__device__ __half g_w2t[(size_t)HID * HID];
__device__ __half g_w3t[(size_t)NCLS_PAD * HID];

// ---------------------------------------------------------------- helpers
DINL uint32_t s2u(const void* p) {
    uint32_t a;
    asm("{ .reg .u64 t; cvta.to.shared.u64 t, %1; cvt.u32.u64 %0, t; }"
        : "=r"(a) : "l"(p));
    return a;
}
DINL void cp_async16(uint32_t s, const void* g) {
    asm volatile("cp.async.cg.shared.global [%0], [%1], 16;" :: "r"(s), "l"(g));
}
DINL void cp_commit() { asm volatile("cp.async.commit_group;" ::: "memory"); }
#define CP_WAIT(n) asm volatile("cp.async.wait_group %0;" :: "n"(n) : "memory")

DINL uint4 lds128(uint32_t a) {
    uint4 v;
    asm volatile("ld.shared.v4.b32 {%0,%1,%2,%3}, [%4];"
                 : "=r"(v.x), "=r"(v.y), "=r"(v.z), "=r"(v.w) : "r"(a));
    return v;
}
DINL void mma16816(float* d, uint32_t a0, uint32_t a1, uint32_t a2, uint32_t a3,
                   uint32_t b0, uint32_t b1) {
    asm volatile(
        "mma.sync.aligned.m16n8k16.row.col.f32.f16.f16.f32 "
        "{%0,%1,%2,%3}, {%4,%5,%6,%7}, {%8,%9}, {%0,%1,%2,%3};"
        : "+f"(d[0]), "+f"(d[1]), "+f"(d[2]), "+f"(d[3])
        : "r"(a0), "r"(a1), "r"(a2), "r"(a3), "r"(b0), "r"(b1));
}
// 32-wide K-permutation
DINL int perm32(int j) {
    const int jj = j & 15;
    return 8 * ((jj >> 1) & 3) + 4 * ((j >> 4) & 1) + 2 * ((jj >> 3) & 1) + (jj & 1);
}

// ------------------------------------------------------------------ GEMM
// A [M,K] fp16 row-major (perm32 within 32-groups), Bt [Npad,K] fp16 same,
// Cv: fp16 (perm32, layers 1/2) or f32 plain (layer 3).
// flags: bit0 relu, bit1 fp16-perm32 output (else f32 plain).
__global__ __launch_bounds__(256, 1)
void mlp_gemm_h(const __half* __restrict__ A, const __half* __restrict__ Bt,
                const float* __restrict__ bias, void* __restrict__ Cv,
                int K, int N, int Mt, int Nt, int flags) {
    extern __shared__ char smem[];
    const uint32_t sb = s2u(smem);
    const int tid = threadIdx.x;
    const int wid = tid >> 5, lid = tid & 31;
    const int warp_m = wid & 1;           // 0..1  (64 rows)
    const int warp_n = wid >> 1;          // 0..3  (64 cols)
    const int lg = lid >> 2;              // 0..7
    const int lc = lid & 3;               // 0..3
    const int ktiles = K / BK;
    const int ntile = Mt * Nt;
    const int do_relu = flags & 1, do_h16 = flags & 2;

    int idx = blockIdx.x;
    if (idx >= ntile) return;

    // per-thread load assignment (constant across tiles/kts):
    // each sub-stage: A 512 chunks (2/thread), B 1024 (4/thread)
    const int ld_row = tid >> 2, ld_j = tid & 3;       // row block, 16B lane
    const uint32_t a_dst0 = sb + ld_row * 64 + ld_j * 16;
    const uint32_t b_dst0 = sb + B_OFF + ld_row * 64 + ld_j * 16;
    const size_t a_src0 = (size_t)ld_row * K + ld_j * 8;   // elements

    auto load_stage = [&](const __half* Ag, const __half* Bg, int kt, int buf) {
        const __half* ap = Ag + (size_t)kt * BK;
        const uint32_t ab = a_dst0 + buf * A_ST;
#pragma unroll
        for (int h = 0; h < 2; h++)
#pragma unroll
            for (int t = 0; t < 2; t++)
                cp_async16(ab + h * A_HALF + t * 64 * 64,
                           ap + a_src0 + (size_t)t * 64 * K + h * 32);
        const __half* bp = Bg + (size_t)kt * BK;
        const uint32_t bb = b_dst0 + buf * B_ST;
#pragma unroll
        for (int h = 0; h < 2; h++)
#pragma unroll
            for (int t = 0; t < 4; t++)
                cp_async16(bb + h * B_HALF + t * 64 * 64,
                           bp + a_src0 + (size_t)t * 64 * K + h * 32);
    };

    int m0 = (idx % Mt) * BM, n0 = (idx / Mt) * BN;
    const __half* Ag = A + (size_t)m0 * K;
    const __half* Bg = Bt + (size_t)n0 * K;

    for (int s = 0; s < STAGES - 1; s++) { load_stage(Ag, Bg, s, s); cp_commit(); }

    // fragment base byte addrs (buffer 0); sub-stage rows are 64B
    const uint32_t a_t0 = sb + (warp_m * 64 + lg) * 64 + 16 * lc;
    const uint32_t b_t0 = sb + B_OFF + (warp_n * 64 + lg) * 64 + 16 * lc;

    for (;;) {
        const int nidx = idx + GRID;
        const int valid = nidx < ntile;
        const __half* Agn = valid ? A + (size_t)((nidx % Mt) * BM) * K : Ag;
        const __half* Bgn = valid ? Bt + (size_t)((nidx / Mt) * BN) * K : Bg;

        float acc[MF][NF][4];
#pragma unroll
        for (int i = 0; i < MF; i++)
#pragma unroll
            for (int j = 0; j < NF; j++)
#pragma unroll
                for (int r = 0; r < 4; r++) acc[i][j][r] = 0.f;

        for (int kt = 0; kt < ktiles; kt++) {
            const int b = kt & (STAGES - 1);
            CP_WAIT(STAGES - 2);
            __syncthreads();

            const int nk = kt + STAGES - 1;
            if (nk < ktiles)  load_stage(Ag, Bg, nk, nk & (STAGES - 1));
            else if (valid)   load_stage(Agn, Bgn, nk - ktiles, nk & (STAGES - 1));
            cp_commit();

#pragma unroll
            for (int h = 0; h < 2; h++) {
                const uint32_t ab = a_t0 + b * A_ST + h * A_HALF;
                const uint32_t bb = b_t0 + b * B_ST + h * B_HALF;

                // one lds.128 per fragment row covers both k16 groups:
                //   .x={a0,a1} g0  .y={a2,a3} g0  .z,.w same for g1
                uint4 af[MF][2];
#pragma unroll
                for (int mf = 0; mf < MF; mf++) {
                    af[mf][0] = lds128(ab + mf * 1024);        // row lg
                    af[mf][1] = lds128(ab + mf * 1024 + 512);  // row lg+8
                }
                uint4 bf[NF];
#pragma unroll
                for (int nf = 0; nf < NF; nf++)
                    bf[nf] = lds128(bb + nf * 512);            // col lg
#pragma unroll
                for (int mf = 0; mf < MF; mf++)
#pragma unroll
                    for (int nf = 0; nf < NF; nf++) {
                        mma16816(acc[mf][nf], af[mf][0].x, af[mf][1].x,
                                 af[mf][0].y, af[mf][1].y, bf[nf].x, bf[nf].y);
                        mma16816(acc[mf][nf], af[mf][0].z, af[mf][1].z,
                                 af[mf][0].w, af[mf][1].w, bf[nf].z, bf[nf].w);
                    }
            }
        }

        // ---- epilogue (next tile's stages already streaming)
        float bvv[NF][2];
#pragma unroll
        for (int nf = 0; nf < NF; nf++) {
            const int c = n0 + warp_n * 64 + nf * 8 + 2 * lc;
            bvv[nf][0] = (c < N) ? __ldg(bias + c) : 0.f;
            bvv[nf][1] = (c + 1 < N) ? __ldg(bias + c + 1) : 0.f;
        }
#pragma unroll
        for (int mf = 0; mf < MF; mf++) {
#pragma unroll
            for (int r2 = 0; r2 < 2; r2++) {
                const int m = m0 + warp_m * 64 + mf * 16 + lg + r2 * 8;
#pragma unroll
                for (int nf = 0; nf < NF; nf++) {
                    const int c = n0 + warp_n * 64 + nf * 8 + 2 * lc;
                    float v0 = acc[mf][nf][r2 * 2 + 0] + bvv[nf][0];
                    float v1 = acc[mf][nf][r2 * 2 + 1] + bvv[nf][1];
                    if (do_relu) { v0 = fmaxf(v0, 0.f); v1 = fmaxf(v1, 0.f); }
                    if (do_h16) {
                        // perm32 slot of logical pair (c,c+1):
                        // phys = 8*lc + 4*((nf>>1)&1) + 2*(nf&1)
                        __half* crow = (__half*)Cv + (size_t)m * N;
                        const int pidx = (c & ~31) + 8 * lc +
                                         4 * ((nf >> 1) & 1) + 2 * (nf & 1);
                        *(__half2*)(crow + pidx) = __floats2half2_rn(v0, v1);
                    } else if (c < N) {
                        float* crow = (float*)Cv + (size_t)m * N;
                        *(float2*)(crow + c) = make_float2(v0, v1);
                    }
                }
            }
        }

        if (!valid) break;
        idx = nidx;
        m0 = (idx % Mt) * BM; n0 = (idx / Mt) * BN;
        Ag = Agn; Bg = Bgn;
    }
}

// ---------------------------------------------------- fused prep (1 launch)
__device__ void transpose_job(const float* __restrict__ s, __half* __restrict__ d,
                              int R, int C, int bx, int by) {
    __shared__ float t[32][33];
    const int tid = threadIdx.x;
    const int x = tid & 31, y = tid >> 5;   // 32 x 8
    const int c0 = bx * 32, r0 = by * 32;
#pragma unroll
    for (int i = y; i < 32; i += 8) {
        int r = r0 + i, c = c0 + x;
        t[i][x] = (c < C) ? s[(size_t)r * C + c] : 0.f;
    }
    __syncthreads();
#pragma unroll
    for (int i = y; i < 32; i += 8) {
        int cc = c0 + i, rr = r0 + x;        // cc = out row (N), rr = K pos
        int rp = (rr & ~31) | perm32(rr & 31);
        d[(size_t)cc * R + rp] = __float2half_rn(t[x][i]);
    }
}

constexpr int G_W1 = (HID / 32) * (IN / 32);        // 8192
constexpr int G_W2 = (HID / 32) * (HID / 32);       // 16384
constexpr int G_W3 = (NCLS_PAD / 32) * (HID / 32);  // 4096
constexpr int G_X  = (BATCH * IN) / 8192;           // 1024 (32 floats/thread)
constexpr int G_PREP = G_W1 + G_W2 + G_W3 + G_X;

__global__ __launch_bounds__(256)
void prep_all(const float* __restrict__ w1, const float* __restrict__ w2,
              const float* __restrict__ w3, const float* __restrict__ x,
              __half* __restrict__ w1t, __half* __restrict__ w2t,
              __half* __restrict__ w3t, __half* __restrict__ xr) {
    int id = blockIdx.x;
    if (id < G_W1) {
        transpose_job(w1, w1t, IN, HID, id % (HID / 32), id / (HID / 32));
        return;
    }
    id -= G_W1;
    if (id < G_W2) {
        transpose_job(w2, w2t, HID, HID, id % (HID / 32), id / (HID / 32));
        return;
    }
    id -= G_W2;
    if (id < G_W3) {
        transpose_job(w3, w3t, HID, NCLS, id % (NCLS_PAD / 32), id / (NCLS_PAD / 32));
        return;
    }
    id -= G_W3;
    // x: fp16-convert + perm32; 32 floats/thread (one 32-group)
    const size_t base = (size_t)id * 8192 + threadIdx.x * 32;
    float f[32];
#pragma unroll
    for (int i = 0; i < 32; i += 4) *(float4*)&f[i] = *(const float4*)(x + base + i);
    __half h[32];
#pragma unroll
    for (int j = 0; j < 32; j++) h[perm32(j)] = __float2half_rn(f[j]);
#pragma unroll
    for (int i = 0; i < 4; i++)
        *(uint4*)(xr + base + i * 8) = *(uint4*)&h[i * 8];
}

// ----------------------------------------------------------------- launcher
extern "C" void kernel_launch(void* const* d_in, const int* in_sizes, int n_in,
                              void* d_out, int out_size) {
    (void)in_sizes; (void)n_in; (void)out_size;
    const float* x  = (const float*)d_in[0];
    const float* w1 = (const float*)d_in[1];
    const float* b1 = (const float*)d_in[2];
    const float* w2 = (const float*)d_in[3];
    const float* b2 = (const float*)d_in[4];
    const float* w3 = (const float*)d_in[5];
    const float* b3 = (const float*)d_in[6];

    __half *h1, *h2, *xr, *w1t, *w2t, *w3t;
    cudaGetSymbolAddress((void**)&h1,  g_h1);
    cudaGetSymbolAddress((void**)&h2,  g_h2);
    cudaGetSymbolAddress((void**)&xr,  g_xr);
    cudaGetSymbolAddress((void**)&w1t, g_w1t);
    cudaGetSymbolAddress((void**)&w2t, g_w2t);
    cudaGetSymbolAddress((void**)&w3t, g_w3t);

    cudaFuncSetAttribute(mlp_gemm_h,
                         cudaFuncAttributeMaxDynamicSharedMemorySize, SMEM_TOT);

    prep_all<<<G_PREP, 256>>>(w1, w2, w3, x, w1t, w2t, w3t, xr);

    const int MT = BATCH / BM;                 // 32
    mlp_gemm_h<<<GRID, 256, SMEM_TOT>>>(
        xr, w1t, b1, h1, IN, HID, MT, HID / BN, /*relu|h16*/ 3);
    mlp_gemm_h<<<GRID, 256, SMEM_TOT>>>(
        h1, w2t, b2, h2, HID, HID, MT, HID / BN, 3);
    mlp_gemm_h<<<GRID, 256, SMEM_TOT>>>(
        h2, w3t, b3, d_out, HID, NCLS, MT, NCLS_PAD / BN, 0);
}